// round 4
// baseline (speedup 1.0000x reference)
#include <cuda_runtime.h>

#define N_NODES   1048576
#define N_GRAPHS  1024
#define F_X       128
#define F_U       128
#define F_CAT     256
#define HIDDEN    512
#define F_OUT     128

#define SPLIT1 2
#define SPLIT2 4

// Scratch (allocation-free rule: __device__ globals)
__device__ int   g_offsets[N_GRAPHS + 1];
__device__ float g_concat[N_GRAPHS * F_CAT];                 // [1024,256]
__device__ float g_h[N_GRAPHS * HIDDEN];                     // [1024,512]
__device__ float g_part1[SPLIT1 * N_GRAPHS * HIDDEN];        // GEMM1 partials
__device__ float g_part2[SPLIT2 * N_GRAPHS * F_OUT];         // GEMM2 partials

// ---------------------------------------------------------------------------
// 1) Segment boundaries from the sorted batch vector (int32 on device).
// ---------------------------------------------------------------------------
__global__ void boundaries_kernel(const int* __restrict__ batch) {
    int i = blockIdx.x * blockDim.x + threadIdx.x;
    if (i >= N_NODES) return;
    int b = batch[i];
    int prev = (i == 0) ? -1 : batch[i - 1];
    int lo = prev + 1; if (lo < 0) lo = 0;
    int hi = b;        if (hi > N_GRAPHS) hi = N_GRAPHS;
    for (int g = lo; g <= hi; g++) g_offsets[g] = i;
    if (i == N_NODES - 1) {
        int lo2 = b + 1; if (lo2 < 0) lo2 = 0;
        for (int g = lo2; g <= N_GRAPHS; g++) g_offsets[g] = N_NODES;
    }
}

// ---------------------------------------------------------------------------
// 2) Segment mean of x -> g_concat[:,0:128]; u -> g_concat[:,128:256].
// ---------------------------------------------------------------------------
__global__ void __launch_bounds__(512) seg_mean_kernel(const float* __restrict__ x,
                                                       const float* __restrict__ u) {
    const int g     = blockIdx.x;
    const int start = g_offsets[g];
    const int end   = g_offsets[g + 1];
    const int tid   = threadIdx.x;
    const int lane  = tid & 31;
    const int grp   = tid >> 5;

    const float* xb = x + (size_t)lane * 4;

    float4 a0 = {0,0,0,0}, a1 = {0,0,0,0}, a2 = {0,0,0,0}, a3 = {0,0,0,0};
    int r = start + grp;
    for (; r + 48 < end; r += 64) {
        float4 v0 = __ldcs((const float4*)(xb + (size_t)(r     ) * F_X));
        float4 v1 = __ldcs((const float4*)(xb + (size_t)(r + 16) * F_X));
        float4 v2 = __ldcs((const float4*)(xb + (size_t)(r + 32) * F_X));
        float4 v3 = __ldcs((const float4*)(xb + (size_t)(r + 48) * F_X));
        a0.x += v0.x; a0.y += v0.y; a0.z += v0.z; a0.w += v0.w;
        a1.x += v1.x; a1.y += v1.y; a1.z += v1.z; a1.w += v1.w;
        a2.x += v2.x; a2.y += v2.y; a2.z += v2.z; a2.w += v2.w;
        a3.x += v3.x; a3.y += v3.y; a3.z += v3.z; a3.w += v3.w;
    }
    for (; r < end; r += 16) {
        float4 v = __ldcs((const float4*)(xb + (size_t)r * F_X));
        a0.x += v.x; a0.y += v.y; a0.z += v.z; a0.w += v.w;
    }
    a0.x += a1.x + a2.x + a3.x;
    a0.y += a1.y + a2.y + a3.y;
    a0.z += a1.z + a2.z + a3.z;
    a0.w += a1.w + a2.w + a3.w;

    __shared__ float4 sm[16][32];
    sm[grp][lane] = a0;
    __syncthreads();
    #pragma unroll
    for (int s = 8; s > 0; s >>= 1) {
        if (grp < s) {
            float4 a = sm[grp][lane];
            float4 b = sm[grp + s][lane];
            a.x += b.x; a.y += b.y; a.z += b.z; a.w += b.w;
            sm[grp][lane] = a;
        }
        __syncthreads();
    }

    if (grp == 0) {
        int cnt = end - start;
        float inv = (cnt > 0) ? (1.0f / (float)cnt) : 0.0f;
        float4 a = sm[0][lane];
        a.x *= inv; a.y *= inv; a.z *= inv; a.w *= inv;
        *(float4*)(g_concat + (size_t)g * F_CAT + lane * 4) = a;
    } else if (grp == 1) {
        float4 v = *(const float4*)(u + (size_t)g * F_U + lane * 4);
        *(float4*)(g_concat + (size_t)g * F_CAT + F_X + lane * 4) = v;
    }
}

// ---------------------------------------------------------------------------
// 3) Split-K tiled SIMT GEMM partial: P[z] = A[:, zK':(z+1)K'] @ B[zK':, :].
//    256 threads; thread computes TMxTN micro-tile. No bias here.
// ---------------------------------------------------------------------------
template <int K, int N, int BM, int BN, int TM, int TN, int SPLIT>
__global__ void __launch_bounds__(256, 4) gemm_split_kernel(const float* __restrict__ A,
                                                            const float* __restrict__ B,
                                                            float* __restrict__ P) {
    constexpr int BK = 16;
    constexpr int KP = K / SPLIT;
    constexpr int TX = BN / TN;
    constexpr int TY = BM / TM;
    static_assert(TX * TY == 256, "bad tile");
    constexpr int A_LOADS = (BM * BK) / 256;
    constexpr int B_LOADS = (BK * BN) / 256;

    __shared__ float As[BK][BM + 4];
    __shared__ float Bs[BK][BN];

    const int bm  = blockIdx.y * BM;
    const int bn  = blockIdx.x * BN;
    const int kz  = blockIdx.z * KP;
    const int tid = threadIdx.x;
    const int tx  = tid % TX;
    const int ty  = tid / TX;

    float acc[TM][TN] = {};

    for (int k0 = kz; k0 < kz + KP; k0 += BK) {
        #pragma unroll
        for (int i = 0; i < A_LOADS; i++) {
            int idx = tid + 256 * i;
            int row = idx / BK, col = idx % BK;
            As[col][row] = A[(size_t)(bm + row) * K + k0 + col];
        }
        #pragma unroll
        for (int i = 0; i < B_LOADS; i++) {
            int idx = tid + 256 * i;
            int row = idx / BN, col = idx % BN;
            Bs[row][col] = B[(size_t)(k0 + row) * N + bn + col];
        }
        __syncthreads();

        #pragma unroll
        for (int k = 0; k < BK; k++) {
            float a[TM], b[TN];
            #pragma unroll
            for (int i = 0; i < TM; i++) a[i] = As[k][ty * TM + i];
            #pragma unroll
            for (int j = 0; j < TN; j++) b[j] = Bs[k][tx * TN + j];
            #pragma unroll
            for (int i = 0; i < TM; i++)
                #pragma unroll
                for (int j = 0; j < TN; j++)
                    acc[i][j] = fmaf(a[i], b[j], acc[i][j]);
        }
        __syncthreads();
    }

    float* Pz = P + (size_t)blockIdx.z * (N_GRAPHS * N);
    #pragma unroll
    for (int i = 0; i < TM; i++) {
        int row = bm + ty * TM + i;
        #pragma unroll
        for (int j = 0; j < TN; j++) {
            int col = bn + tx * TN + j;
            Pz[(size_t)row * N + col] = acc[i][j];
        }
    }
}

// ---------------------------------------------------------------------------
// 4) Deterministic split reduce: C = act(sum_z P[z] + bias). float4 per thread.
// ---------------------------------------------------------------------------
template <int SPLIT, int N, bool RELU>
__global__ void __launch_bounds__(256) reduce_kernel(const float* __restrict__ P,
                                                     const float* __restrict__ bias,
                                                     float* __restrict__ C) {
    constexpr int TOTAL4 = (N_GRAPHS * N) / 4;
    int i = blockIdx.x * blockDim.x + threadIdx.x;
    if (i >= TOTAL4) return;
    float4 s = ((const float4*)P)[i];
    #pragma unroll
    for (int z = 1; z < SPLIT; z++) {
        float4 p = ((const float4*)P)[(size_t)z * TOTAL4 + i];
        s.x += p.x; s.y += p.y; s.z += p.z; s.w += p.w;
    }
    float4 bv = *(const float4*)(bias + (i * 4) % N);
    s.x += bv.x; s.y += bv.y; s.z += bv.z; s.w += bv.w;
    if (RELU) {
        s.x = fmaxf(s.x, 0.0f); s.y = fmaxf(s.y, 0.0f);
        s.z = fmaxf(s.z, 0.0f); s.w = fmaxf(s.w, 0.0f);
    }
    ((float4*)C)[i] = s;
}

// ---------------------------------------------------------------------------
// Launch. Inputs: x, edge_index, edge_attr, u, batch, W1, b1, W2, b2.
// edge_* unused; int64 inputs arrive as int32 on device.
// ---------------------------------------------------------------------------
extern "C" void kernel_launch(void* const* d_in, const int* in_sizes, int n_in,
                              void* d_out, int out_size) {
    const float* x     = (const float*)d_in[0];
    const float* u     = (const float*)d_in[3];
    const int*   batch = (const int*)d_in[4];
    const float* W1    = (const float*)d_in[5];
    const float* b1    = (const float*)d_in[6];
    const float* W2    = (const float*)d_in[7];
    const float* b2    = (const float*)d_in[8];
    float*       out   = (float*)d_out;

    void *p_concat = nullptr, *p_h = nullptr, *p_p1 = nullptr, *p_p2 = nullptr;
    cudaGetSymbolAddress(&p_concat, g_concat);
    cudaGetSymbolAddress(&p_h, g_h);
    cudaGetSymbolAddress(&p_p1, g_part1);
    cudaGetSymbolAddress(&p_p2, g_part2);

    boundaries_kernel<<<(N_NODES + 255) / 256, 256>>>(batch);
    seg_mean_kernel<<<N_GRAPHS, 512>>>(x, u);

    // GEMM1: [1024,256]@[256,512] split-2 -> 512 blocks
    gemm_split_kernel<F_CAT, HIDDEN, 64, 32, 4, 2, SPLIT1>
        <<<dim3(HIDDEN / 32, N_GRAPHS / 64, SPLIT1), 256>>>(
        (const float*)p_concat, W1, (float*)p_p1);
    reduce_kernel<SPLIT1, HIDDEN, true>
        <<<(N_GRAPHS * HIDDEN / 4 + 255) / 256, 256>>>(
        (const float*)p_p1, b1, (float*)p_h);

    // GEMM2: [1024,512]@[512,128] split-4 -> 512 blocks
    gemm_split_kernel<HIDDEN, F_OUT, 32, 32, 2, 2, SPLIT2>
        <<<dim3(F_OUT / 32, N_GRAPHS / 32, SPLIT2), 256>>>(
        (const float*)p_h, W2, (float*)p_p2);
    reduce_kernel<SPLIT2, F_OUT, false>
        <<<(N_GRAPHS * F_OUT / 4 + 255) / 256, 256>>>(
        (const float*)p_p2, b2, out);
}